// round 1
// baseline (speedup 1.0000x reference)
#include <cuda_runtime.h>
#include <math.h>

#define SEQ   2048
#define DM    1024
#define NH    16
#define DH    128
#define HD    2048   // NH*DH

// ---------------- scratch (no allocations allowed) ----------------
__device__ float g_Q[NH * SEQ * DH];
__device__ float g_K[NH * SEQ * DH];
__device__ float g_V[NH * SEQ * DH];
__device__ int   g_mask[SEQ];

// ---------------- mask decode: robust to bool-as-{u8,i32,f32} ----------------
__global__ void decode_mask_kernel(const unsigned char* __restrict__ p)
{
    __shared__ int not_i32, not_f32;
    int t = threadIdx.x;
    if (t == 0) { not_i32 = 0; not_f32 = 0; }
    __syncthreads();
    if (t < 512) {  // first 2048 bytes: safe under every candidate layout
        unsigned w = ((const unsigned*)p)[t];
        if (!(w == 0u || w == 1u))          atomicExch(&not_i32, 1);
        if (!(w == 0u || w == 0x3F800000u)) atomicExch(&not_f32, 1);
    }
    __syncthreads();
    int cls = (!not_i32) ? 0 : ((!not_f32) ? 1 : 2);
    for (int i = t; i < SEQ; i += blockDim.x) {
        int v;
        if (cls == 0)      v = (((const int*)p)[i]   != 0);
        else if (cls == 1) v = (((const float*)p)[i] != 0.0f);
        else               v = (p[i] != 0);
        g_mask[i] = v;
    }
}

// ---------------- projection GEMM: out[h][s][d] = X @ W + b ----------------
// X:[SEQ,DM] fp32, W:[DM,HD] fp32, b:[HD]. 64x64 tile, K-tile 16, 4x4 micro.
__global__ __launch_bounds__(256) void proj_kernel(
    const float* __restrict__ X, const float* __restrict__ W,
    const float* __restrict__ b, float* __restrict__ outp)
{
    __shared__ float Xs[64][17];
    __shared__ float Ws[16][64];
    int t  = threadIdx.x;
    int tx = t & 15, ty = t >> 4;
    int m0 = blockIdx.y << 6, n0 = blockIdx.x << 6;
    float acc[4][4] = {};
    for (int k0 = 0; k0 < DM; k0 += 16) {
        #pragma unroll
        for (int u = 0; u < 4; u++) {
            int i = t + u * 256;               // 0..1023
            int r = i >> 4, kk = i & 15;
            Xs[r][kk] = X[(m0 + r) * DM + k0 + kk];
        }
        #pragma unroll
        for (int u = 0; u < 4; u++) {
            int i = t + u * 256;
            int kk = i >> 6, c = i & 63;
            Ws[kk][c] = W[(k0 + kk) * HD + n0 + c];
        }
        __syncthreads();
        #pragma unroll
        for (int kk = 0; kk < 16; kk++) {
            float a0 = Xs[ty * 4 + 0][kk];
            float a1 = Xs[ty * 4 + 1][kk];
            float a2 = Xs[ty * 4 + 2][kk];
            float a3 = Xs[ty * 4 + 3][kk];
            float4 bv = *(const float4*)&Ws[kk][tx * 4];
            acc[0][0] += a0 * bv.x; acc[0][1] += a0 * bv.y; acc[0][2] += a0 * bv.z; acc[0][3] += a0 * bv.w;
            acc[1][0] += a1 * bv.x; acc[1][1] += a1 * bv.y; acc[1][2] += a1 * bv.z; acc[1][3] += a1 * bv.w;
            acc[2][0] += a2 * bv.x; acc[2][1] += a2 * bv.y; acc[2][2] += a2 * bv.z; acc[2][3] += a2 * bv.w;
            acc[3][0] += a3 * bv.x; acc[3][1] += a3 * bv.y; acc[3][2] += a3 * bv.z; acc[3][3] += a3 * bv.w;
        }
        __syncthreads();
    }
    #pragma unroll
    for (int i = 0; i < 4; i++) {
        int row = m0 + ty * 4 + i;
        #pragma unroll
        for (int j = 0; j < 4; j++) {
            int col = n0 + tx * 4 + j;
            // head-major store: [h][s][d]
            outp[(((col >> 7) * SEQ) + row) * DH + (col & 127)] = acc[i][j] + b[col];
        }
    }
}

// ---------------- fused attention: flash-style per (head, 64-query tile) ----------------
// Dynamic smem layout (floats):
//   Qs   [64][129]   @ 0       (8256)
//   KV   8320        @ 8256    (KsT[128][65] for S-phase; Vs[64][128] for PV-phase)
//   Ps   [64][65]    @ 16576   (4160)
//   red  [256]       @ 20736
//   mrow [64]        @ 20992
//   lrow [64]        @ 21056
//   alph [64]        @ 21120
//   mq   [64](int)   @ 21184
//   mk   [64](int)   @ 21248
// total 21312 floats = 85248 bytes
#define ATTN_SMEM_FLOATS 21312

__global__ __launch_bounds__(256, 2) void attn_kernel(float* __restrict__ out)
{
    extern __shared__ float sm[];
    float* Qs   = sm;
    float* KV   = sm + 8256;
    float* Ps   = sm + 16576;
    float* red  = sm + 20736;
    float* mrow = sm + 20992;
    float* lrow = sm + 21056;
    float* alph = sm + 21120;
    int*   mq   = (int*)(sm + 21184);
    int*   mk   = (int*)(sm + 21248);

    const int t  = threadIdx.x;
    const int tx = t & 15, ty = t >> 4;
    const int h  = blockIdx.y;
    const int q0 = blockIdx.x << 6;

    const float MASKED_SCALE = -1.0e9f * 0.08838834764831845f;  // -1e9 / sqrt(128)

    if (t < 64) { mrow[t] = -INFINITY; lrow[t] = 0.0f; mq[t] = g_mask[q0 + t]; }

    // load Q tile [64][128] -> Qs (stride 129)
    const float* Qg = g_Q + (h * SEQ + q0) * DH;
    #pragma unroll
    for (int u = 0; u < 8; u++) {
        int i = t + u * 256;                 // float4 index 0..2047
        float4 v = ((const float4*)Qg)[i];
        int r = i >> 5, dd = (i & 31) << 2;
        float* q = Qs + r * 129 + dd;
        q[0] = v.x; q[1] = v.y; q[2] = v.z; q[3] = v.w;
    }

    float acc[4][8];
    #pragma unroll
    for (int i = 0; i < 4; i++)
        #pragma unroll
        for (int j = 0; j < 8; j++) acc[i][j] = 0.0f;

    for (int kt = 0; kt < SEQ / 64; kt++) {
        const int k0 = kt << 6;
        __syncthreads();   // prior PV reads of Ps/KV complete

        // load K tile transposed: KsT[d][r] = K[k0+r][d]   (stride 65 -> conflict-free)
        const float* Kg = g_K + (h * SEQ + k0) * DH;
        #pragma unroll
        for (int u = 0; u < 8; u++) {
            int i = t + u * 256;
            int r = i >> 5, dd = (i & 31) << 2;
            float4 v = *(const float4*)(Kg + r * DH + dd);
            KV[(dd + 0) * 65 + r] = v.x;
            KV[(dd + 1) * 65 + r] = v.y;
            KV[(dd + 2) * 65 + r] = v.z;
            KV[(dd + 3) * 65 + r] = v.w;
        }
        if (t < 64) mk[t] = g_mask[k0 + t];
        __syncthreads();

        // S = Q @ K^T  (4x4 micro on 16x16 threads)
        float s00=0,s01=0,s02=0,s03=0, s10=0,s11=0,s12=0,s13=0;
        float s20=0,s21=0,s22=0,s23=0, s30=0,s31=0,s32=0,s33=0;
        {
            const float* q0p = Qs + (ty * 4 + 0) * 129;
            const float* q1p = Qs + (ty * 4 + 1) * 129;
            const float* q2p = Qs + (ty * 4 + 2) * 129;
            const float* q3p = Qs + (ty * 4 + 3) * 129;
            const float* kp  = KV + (tx << 2);
            #pragma unroll 8
            for (int d = 0; d < DH; d++) {
                float a0 = q0p[d], a1 = q1p[d], a2 = q2p[d], a3 = q3p[d];
                float b0 = kp[0], b1 = kp[1], b2 = kp[2], b3 = kp[3];
                kp += 65;
                s00 += a0*b0; s01 += a0*b1; s02 += a0*b2; s03 += a0*b3;
                s10 += a1*b0; s11 += a1*b1; s12 += a1*b2; s13 += a1*b3;
                s20 += a2*b0; s21 += a2*b1; s22 += a2*b2; s23 += a2*b3;
                s30 += a3*b0; s31 += a3*b1; s32 += a3*b2; s33 += a3*b3;
            }
        }
        // apply multiplicative mask + scale, write Ps
        {
            float sv[4][4] = {{s00,s01,s02,s03},{s10,s11,s12,s13},{s20,s21,s22,s23},{s30,s31,s32,s33}};
            #pragma unroll
            for (int i = 0; i < 4; i++) {
                int r = ty * 4 + i;
                int mr = mq[r];
                float* pr = Ps + r * 65 + (tx << 2);
                #pragma unroll
                for (int j = 0; j < 4; j++) {
                    int c = (tx << 2) + j;
                    pr[j] = (mr & mk[c]) ? sv[i][j] * MASKED_SCALE : 0.0f;
                }
            }
        }
        __syncthreads();   // S-phase KV reads done; Ps complete

        // issue V global loads now (overlap with softmax reductions)
        const float* Vg = g_V + (h * SEQ + k0) * DH;
        float4 vbuf[8];
        #pragma unroll
        for (int u = 0; u < 8; u++) vbuf[u] = ((const float4*)Vg)[t + u * 256];

        // row max partial (4 threads per row, 16 cols each)
        {
            int r = t >> 2, part = t & 3;
            const float* pr = Ps + r * 65 + part * 16;
            float mx = -INFINITY;
            #pragma unroll
            for (int c = 0; c < 16; c++) mx = fmaxf(mx, pr[c]);
            red[t] = mx;
        }
        __syncthreads();
        if (t < 64) {
            float mx = fmaxf(fmaxf(red[t*4], red[t*4+1]), fmaxf(red[t*4+2], red[t*4+3]));
            float mold = mrow[t];
            float mnew = fmaxf(mold, mx);
            mrow[t] = mnew;
            alph[t] = __expf(mold - mnew);   // exp(-inf)=0 on first tile
        }
        __syncthreads();
        // exponentiate + partial row sum
        {
            int r = t >> 2, part = t & 3;
            float mn = mrow[r];
            float* pr = Ps + r * 65 + part * 16;
            float sum = 0.0f;
            #pragma unroll
            for (int c = 0; c < 16; c++) {
                float p = __expf(pr[c] - mn);
                pr[c] = p; sum += p;
            }
            red[t] = sum;
        }
        // store V to smem (linear: Vs[c][d] == KV[i*4])
        #pragma unroll
        for (int u = 0; u < 8; u++) ((float4*)KV)[t + u * 256] = vbuf[u];
        __syncthreads();
        if (t < 64)
            lrow[t] = lrow[t] * alph[t] + (red[t*4] + red[t*4+1] + red[t*4+2] + red[t*4+3]);

        // PV: acc = acc*alpha + P @ V   (4x8 micro on 16x16 threads)
        {
            float al0 = alph[ty*4+0], al1 = alph[ty*4+1], al2 = alph[ty*4+2], al3 = alph[ty*4+3];
            #pragma unroll
            for (int j = 0; j < 8; j++) { acc[0][j]*=al0; acc[1][j]*=al1; acc[2][j]*=al2; acc[3][j]*=al3; }
            const float* p0 = Ps + (ty*4+0) * 65;
            const float* p1 = Ps + (ty*4+1) * 65;
            const float* p2 = Ps + (ty*4+2) * 65;
            const float* p3 = Ps + (ty*4+3) * 65;
            const float* vp = KV + (tx << 3);
            #pragma unroll 4
            for (int c = 0; c < 64; c++) {
                float a0 = p0[c], a1 = p1[c], a2 = p2[c], a3 = p3[c];
                float4 v0 = *(const float4*)(vp);
                float4 v1 = *(const float4*)(vp + 4);
                vp += 128;
                acc[0][0]+=a0*v0.x; acc[0][1]+=a0*v0.y; acc[0][2]+=a0*v0.z; acc[0][3]+=a0*v0.w;
                acc[0][4]+=a0*v1.x; acc[0][5]+=a0*v1.y; acc[0][6]+=a0*v1.z; acc[0][7]+=a0*v1.w;
                acc[1][0]+=a1*v0.x; acc[1][1]+=a1*v0.y; acc[1][2]+=a1*v0.z; acc[1][3]+=a1*v0.w;
                acc[1][4]+=a1*v1.x; acc[1][5]+=a1*v1.y; acc[1][6]+=a1*v1.z; acc[1][7]+=a1*v1.w;
                acc[2][0]+=a2*v0.x; acc[2][1]+=a2*v0.y; acc[2][2]+=a2*v0.z; acc[2][3]+=a2*v0.w;
                acc[2][4]+=a2*v1.x; acc[2][5]+=a2*v1.y; acc[2][6]+=a2*v1.z; acc[2][7]+=a2*v1.w;
                acc[3][0]+=a3*v0.x; acc[3][1]+=a3*v0.y; acc[3][2]+=a3*v0.z; acc[3][3]+=a3*v0.w;
                acc[3][4]+=a3*v1.x; acc[3][5]+=a3*v1.y; acc[3][6]+=a3*v1.z; acc[3][7]+=a3*v1.w;
            }
        }
    }
    __syncthreads();   // last lrow update visible

    // epilogue: out[s][h*128+d] = acc / l
    #pragma unroll
    for (int i = 0; i < 4; i++) {
        int r = ty * 4 + i;
        float inv = 1.0f / lrow[r];
        float* op = out + (size_t)(q0 + r) * HD + h * DH + (tx << 3);
        float4 o0, o1;
        o0.x = acc[i][0]*inv; o0.y = acc[i][1]*inv; o0.z = acc[i][2]*inv; o0.w = acc[i][3]*inv;
        o1.x = acc[i][4]*inv; o1.y = acc[i][5]*inv; o1.z = acc[i][6]*inv; o1.w = acc[i][7]*inv;
        ((float4*)op)[0] = o0;
        ((float4*)op)[1] = o1;
    }
}

// ---------------- launch ----------------
extern "C" void kernel_launch(void* const* d_in, const int* in_sizes, int n_in,
                              void* d_out, int out_size)
{
    const float* X          = (const float*)d_in[0];
    const unsigned char* mp = (const unsigned char*)d_in[1];
    const float* Wq = (const float*)d_in[2];
    const float* bq = (const float*)d_in[3];
    const float* Wk = (const float*)d_in[4];
    const float* bk = (const float*)d_in[5];
    const float* Wv = (const float*)d_in[6];
    const float* bv = (const float*)d_in[7];
    float* out = (float*)d_out;

    float *Qp, *Kp, *Vp;
    cudaGetSymbolAddress((void**)&Qp, g_Q);
    cudaGetSymbolAddress((void**)&Kp, g_K);
    cudaGetSymbolAddress((void**)&Vp, g_V);

    decode_mask_kernel<<<1, 512>>>(mp);

    dim3 pgrid(HD / 64, SEQ / 64);
    proj_kernel<<<pgrid, 256>>>(X, Wq, bq, Qp);
    proj_kernel<<<pgrid, 256>>>(X, Wk, bk, Kp);
    proj_kernel<<<pgrid, 256>>>(X, Wv, bv, Vp);

    const int smem_bytes = ATTN_SMEM_FLOATS * (int)sizeof(float);
    cudaFuncSetAttribute(attn_kernel, cudaFuncAttributeMaxDynamicSharedMemorySize, smem_bytes);
    attn_kernel<<<dim3(SEQ / 64, NH), 256, smem_bytes>>>(out);
}

// round 2
// speedup vs baseline: 1.9578x; 1.9578x over previous
#include <cuda_runtime.h>
#include <math.h>

#define SEQ   2048
#define DM    1024
#define NH    16
#define DH    128
#define HD    2048   // NH*DH

// ---------------- scratch (no allocations allowed) ----------------
__device__ float g_Q[NH * SEQ * DH];   // compacted masked rows, head-major
__device__ float g_K[NH * SEQ * DH];   // compacted masked rows, head-major
__device__ float g_V[NH * SEQ * DH];   // full, head-major
__device__ float g_vmean[NH * DH];
__device__ int   g_mask[SEQ];
__device__ int   g_midx[SEQ];          // compacted masked row indices (padded w/ 0)
__device__ int   g_kbest[NH * SEQ];    // per masked row: argmin k (original index)
__device__ int   g_mcount;
__device__ int   g_mcount64;

// ---------------- mask decode (bool-as-{u8,i32,f32}) + compaction ----------------
__global__ void mask_setup_kernel(const unsigned char* __restrict__ p)
{
    __shared__ int sm[SEQ];
    __shared__ int cnt[64];
    __shared__ int base[65];
    __shared__ int not_i32, not_f32;
    int t = threadIdx.x;               // 1024 threads
    if (t == 0) { not_i32 = 0; not_f32 = 0; }
    __syncthreads();
    if (t < 512) {                     // first 2048 bytes: safe under all layouts
        unsigned w = ((const unsigned*)p)[t];
        if (!(w == 0u || w == 1u))          atomicExch(&not_i32, 1);
        if (!(w == 0u || w == 0x3F800000u)) atomicExch(&not_f32, 1);
    }
    __syncthreads();
    int cls = (!not_i32) ? 0 : ((!not_f32) ? 1 : 2);
    for (int i = t; i < SEQ; i += 1024) {
        int v;
        if (cls == 0)      v = (((const int*)p)[i]   != 0);
        else if (cls == 1) v = (((const float*)p)[i] != 0.0f);
        else               v = (p[i] != 0);
        sm[i] = v; g_mask[i] = v;
    }
    __syncthreads();
    if (t < 64) {
        int c = 0;
        for (int i = 0; i < 32; i++) c += sm[t * 32 + i];
        cnt[t] = c;
    }
    __syncthreads();
    if (t == 0) {
        int acc = 0;
        for (int c = 0; c < 64; c++) { base[c] = acc; acc += cnt[c]; }
        base[64] = acc;
        g_mcount = acc;
        g_mcount64 = (acc + 63) & ~63;
    }
    __syncthreads();
    if (t < 64) {
        int pos = base[t];
        for (int i = 0; i < 32; i++)
            if (sm[t * 32 + i]) g_midx[pos++] = t * 32 + i;
    }
    __syncthreads();
    int mc = base[64];
    for (int i = t; i < SEQ; i += 1024)
        if (i >= mc) g_midx[i] = 0;
}

// ---------------- projection GEMM (optionally row-gathered) ----------------
// out[h][row_c][d] = X[src_row] @ W + b, head-major.
__global__ __launch_bounds__(256) void proj_kernel(
    const float* __restrict__ X, const float* __restrict__ W,
    const float* __restrict__ b, float* __restrict__ outp, int gather)
{
    __shared__ float Xs[64][17];
    __shared__ float Ws[16][64];
    __shared__ int   ridx[64];
    int t  = threadIdx.x;
    int tx = t & 15, ty = t >> 4;
    int m0 = blockIdx.y << 6, n0 = blockIdx.x << 6;
    if (gather && m0 >= g_mcount64) return;
    if (t < 64) ridx[t] = gather ? g_midx[m0 + t] : (m0 + t);
    __syncthreads();
    float acc[4][4] = {};
    for (int k0 = 0; k0 < DM; k0 += 16) {
        #pragma unroll
        for (int u = 0; u < 4; u++) {
            int i = t + u * 256;
            int r = i >> 4, kk = i & 15;
            Xs[r][kk] = X[ridx[r] * DM + k0 + kk];
        }
        #pragma unroll
        for (int u = 0; u < 4; u++) {
            int i = t + u * 256;
            int kk = i >> 6, c = i & 63;
            Ws[kk][c] = W[(k0 + kk) * HD + n0 + c];
        }
        __syncthreads();
        #pragma unroll
        for (int kk = 0; kk < 16; kk++) {
            float a0 = Xs[ty * 4 + 0][kk];
            float a1 = Xs[ty * 4 + 1][kk];
            float a2 = Xs[ty * 4 + 2][kk];
            float a3 = Xs[ty * 4 + 3][kk];
            float4 bv = *(const float4*)&Ws[kk][tx * 4];
            acc[0][0] += a0 * bv.x; acc[0][1] += a0 * bv.y; acc[0][2] += a0 * bv.z; acc[0][3] += a0 * bv.w;
            acc[1][0] += a1 * bv.x; acc[1][1] += a1 * bv.y; acc[1][2] += a1 * bv.z; acc[1][3] += a1 * bv.w;
            acc[2][0] += a2 * bv.x; acc[2][1] += a2 * bv.y; acc[2][2] += a2 * bv.z; acc[2][3] += a2 * bv.w;
            acc[3][0] += a3 * bv.x; acc[3][1] += a3 * bv.y; acc[3][2] += a3 * bv.z; acc[3][3] += a3 * bv.w;
        }
        __syncthreads();
    }
    #pragma unroll
    for (int i = 0; i < 4; i++) {
        int row = m0 + ty * 4 + i;     // compacted (or original) row
        #pragma unroll
        for (int j = 0; j < 4; j++) {
            int col = n0 + tx * 4 + j;
            outp[(((col >> 7) * SEQ) + row) * DH + (col & 127)] = acc[i][j] + b[col];
        }
    }
}

// ---------------- V column means (deterministic reduction) ----------------
__global__ void vmean_kernel()
{
    __shared__ float red[8][33];
    int blk = blockIdx.x;              // 64 = 16 heads * 4 d-chunks
    int h = blk >> 2, ch = blk & 3;
    int t = threadIdx.x;               // 256
    int d = t & 31, part = t >> 5;
    const float* V = g_V + (size_t)(h * SEQ) * DH + ch * 32 + d;
    float s = 0.0f;
    int r0 = part * 256;
    for (int r = r0; r < r0 + 256; r++) s += V[(size_t)r * DH];
    red[part][d] = s;
    __syncthreads();
    if (t < 32) {
        float acc = 0.0f;
        #pragma unroll
        for (int p = 0; p < 8; p++) acc += red[p][t];
        g_vmean[h * DH + ch * 32 + t] = acc * (1.0f / 2048.0f);
    }
}

// ---------------- score + argmin over masked x masked pairs ----------------
// smem (floats): Qs[64][129]@0, KsT[128][65]@8256, rv[64][16]@16576,
//                ri(int)[64][16]@17600, bestv[64]@18624, besti(int)[64]@18688
#define SC_SMEM_FLOATS 18752

__global__ __launch_bounds__(256, 2) void score_kernel(
    const float* __restrict__ Qc, const float* __restrict__ Kc)
{
    extern __shared__ float sm[];
    float* Qs    = sm;
    float* KsT   = sm + 8256;
    float* rv    = sm + 16576;
    int*   ri    = (int*)(sm + 17600);
    float* bestv = sm + 18624;
    int*   besti = (int*)(sm + 18688);

    const int t  = threadIdx.x;
    const int tx = t & 15, ty = t >> 4;
    const int h  = blockIdx.y;
    const int q0 = blockIdx.x << 6;
    const int mc   = g_mcount;
    const int mc64 = g_mcount64;
    if (q0 >= mc) return;

    // load Q tile [64][128] -> stride 129
    const float* Qg = Qc + (size_t)(h * SEQ + q0) * DH;
    #pragma unroll
    for (int u = 0; u < 8; u++) {
        int i = t + u * 256;
        float4 v = ((const float4*)Qg)[i];
        int r = i >> 5, dd = (i & 31) << 2;
        float* q = Qs + r * 129 + dd;
        q[0] = v.x; q[1] = v.y; q[2] = v.z; q[3] = v.w;
    }
    if (t < 64) { bestv[t] = INFINITY; besti[t] = 0; }

    const int nkt = mc64 >> 6;
    for (int kt = 0; kt < nkt; kt++) {
        const int k0 = kt << 6;
        __syncthreads();   // Q load done / previous reduce done, KsT free

        const float* Kg = Kc + (size_t)(h * SEQ + k0) * DH;
        #pragma unroll
        for (int u = 0; u < 8; u++) {
            int i = t + u * 256;
            int r = i >> 5, dd = (i & 31) << 2;
            float4 v = *(const float4*)(Kg + r * DH + dd);
            KsT[(dd + 0) * 65 + r] = v.x;
            KsT[(dd + 1) * 65 + r] = v.y;
            KsT[(dd + 2) * 65 + r] = v.z;
            KsT[(dd + 3) * 65 + r] = v.w;
        }
        __syncthreads();

        float s00=0,s01=0,s02=0,s03=0, s10=0,s11=0,s12=0,s13=0;
        float s20=0,s21=0,s22=0,s23=0, s30=0,s31=0,s32=0,s33=0;
        {
            const float* q0p = Qs + (ty * 4 + 0) * 129;
            const float* q1p = Qs + (ty * 4 + 1) * 129;
            const float* q2p = Qs + (ty * 4 + 2) * 129;
            const float* q3p = Qs + (ty * 4 + 3) * 129;
            const float* kp  = KsT + (tx << 2);
            #pragma unroll 8
            for (int d = 0; d < DH; d++) {
                float a0 = q0p[d], a1 = q1p[d], a2 = q2p[d], a3 = q3p[d];
                float b0 = kp[0], b1 = kp[1], b2 = kp[2], b3 = kp[3];
                kp += 65;
                s00 += a0*b0; s01 += a0*b1; s02 += a0*b2; s03 += a0*b3;
                s10 += a1*b0; s11 += a1*b1; s12 += a1*b2; s13 += a1*b3;
                s20 += a2*b0; s21 += a2*b1; s22 += a2*b2; s23 += a2*b3;
                s30 += a3*b0; s31 += a3*b1; s32 += a3*b2; s33 += a3*b3;
            }
        }
        // per-thread argmin over its 4 cols, per row (raw score; scale > 0 irrelevant)
        {
            float svr[4][4] = {{s00,s01,s02,s03},{s10,s11,s12,s13},
                               {s20,s21,s22,s23},{s30,s31,s32,s33}};
            #pragma unroll
            for (int i = 0; i < 4; i++) {
                float bv = INFINITY; int bi = 0;
                #pragma unroll
                for (int j = 0; j < 4; j++) {
                    int c = k0 + (tx << 2) + j;
                    float v = (c < mc) ? svr[i][j] : INFINITY;
                    if (v < bv) { bv = v; bi = c; }
                }
                rv[(ty * 4 + i) * 16 + tx] = bv;
                ri[(ty * 4 + i) * 16 + tx] = bi;
            }
        }
        __syncthreads();
        if (t < 64) {
            float bv = bestv[t]; int bi = besti[t];
            #pragma unroll
            for (int p = 0; p < 16; p++) {
                float v = rv[t * 16 + p];
                if (v < bv) { bv = v; bi = ri[t * 16 + p]; }
            }
            bestv[t] = bv; besti[t] = bi;
        }
    }
    __syncthreads();
    if (t < 64 && q0 + t < mc) {
        int kc = besti[t];                               // compacted index
        g_kbest[h * SEQ + g_midx[q0 + t]] = g_midx[kc];  // original index
    }
}

// ---------------- output assembly ----------------
__global__ void assemble_kernel(float* __restrict__ out)
{
    int s = blockIdx.x;
    int t = threadIdx.x;               // 256
    int msk = g_mask[s];
    #pragma unroll
    for (int i = 0; i < 8; i++) {
        int idx = i * 256 + t;         // h*128 + d
        float val;
        if (msk) {
            int h = idx >> 7, d = idx & 127;
            int kb = g_kbest[h * SEQ + s];
            val = g_V[(size_t)(h * SEQ + kb) * DH + d];
        } else {
            val = g_vmean[idx];
        }
        out[(size_t)s * HD + idx] = val;
    }
}

// ---------------- launch ----------------
extern "C" void kernel_launch(void* const* d_in, const int* in_sizes, int n_in,
                              void* d_out, int out_size)
{
    const float* X          = (const float*)d_in[0];
    const unsigned char* mp = (const unsigned char*)d_in[1];
    const float* Wq = (const float*)d_in[2];
    const float* bq = (const float*)d_in[3];
    const float* Wk = (const float*)d_in[4];
    const float* bk = (const float*)d_in[5];
    const float* Wv = (const float*)d_in[6];
    const float* bv = (const float*)d_in[7];
    float* out = (float*)d_out;

    float *Qp, *Kp, *Vp;
    cudaGetSymbolAddress((void**)&Qp, g_Q);
    cudaGetSymbolAddress((void**)&Kp, g_K);
    cudaGetSymbolAddress((void**)&Vp, g_V);

    mask_setup_kernel<<<1, 1024>>>(mp);

    dim3 pgrid(HD / 64, SEQ / 64);
    proj_kernel<<<pgrid, 256>>>(X, Wq, bq, Qp, 1);   // masked rows only
    proj_kernel<<<pgrid, 256>>>(X, Wk, bk, Kp, 1);   // masked rows only
    proj_kernel<<<pgrid, 256>>>(X, Wv, bv, Vp, 0);   // full

    vmean_kernel<<<64, 256>>>();

    const int sc_bytes = SC_SMEM_FLOATS * (int)sizeof(float);
    cudaFuncSetAttribute(score_kernel, cudaFuncAttributeMaxDynamicSharedMemorySize, sc_bytes);
    score_kernel<<<dim3(SEQ / 64, NH), 256, sc_bytes>>>(Qp, Kp);

    assemble_kernel<<<SEQ, 256>>>(out);
}

// round 3
// speedup vs baseline: 2.9819x; 1.5231x over previous
#include <cuda_runtime.h>
#include <math.h>

typedef unsigned long long ull;

#define SEQ   2048
#define DM    1024
#define NH    16
#define DH    128
#define HD    2048   // NH*DH

// ---------------- scratch ----------------
__device__ float g_Q[NH * SEQ * DH];   // compacted masked rows, head-major
__device__ float g_K[NH * SEQ * DH];
__device__ float g_V[NH * SEQ * DH];   // compacted masked rows too
__device__ float g_xpart[8][DM];
__device__ float g_xmean[DM];
__device__ float g_vmean[HD];
__device__ int   g_mask[SEQ];
__device__ int   g_midx[SEQ];
__device__ int   g_kbest[NH * SEQ];    // per original masked row: compacted argmin k
__device__ int   g_mcount;
__device__ int   g_mcount64;

// ---------------- f32x2 helpers ----------------
__device__ __forceinline__ void fma2(ull& d, ull a, ull b) {
    asm("fma.rn.f32x2 %0, %1, %2, %0;" : "+l"(d) : "l"(a), "l"(b));
}
__device__ __forceinline__ ull packf2(float lo, float hi) {
    ull r; asm("mov.b64 %0, {%1, %2};" : "=l"(r) : "f"(lo), "f"(hi)); return r;
}
__device__ __forceinline__ float f2sum(ull v) {
    float lo, hi; asm("mov.b64 {%0, %1}, %2;" : "=f"(lo), "=f"(hi) : "l"(v));
    return lo + hi;
}

// ---------------- mask decode + compaction ----------------
__global__ void mask_setup_kernel(const unsigned char* __restrict__ p)
{
    __shared__ int sm[SEQ];
    __shared__ int cnt[64];
    __shared__ int base[65];
    __shared__ int not_i32, not_f32;
    int t = threadIdx.x;               // 1024 threads
    if (t == 0) { not_i32 = 0; not_f32 = 0; }
    __syncthreads();
    if (t < 512) {
        unsigned w = ((const unsigned*)p)[t];
        if (!(w == 0u || w == 1u))          atomicExch(&not_i32, 1);
        if (!(w == 0u || w == 0x3F800000u)) atomicExch(&not_f32, 1);
    }
    __syncthreads();
    int cls = (!not_i32) ? 0 : ((!not_f32) ? 1 : 2);
    for (int i = t; i < SEQ; i += 1024) {
        int v;
        if (cls == 0)      v = (((const int*)p)[i]   != 0);
        else if (cls == 1) v = (((const float*)p)[i] != 0.0f);
        else               v = (p[i] != 0);
        sm[i] = v; g_mask[i] = v;
    }
    __syncthreads();
    if (t < 64) {
        int c = 0;
        for (int i = 0; i < 32; i++) c += sm[t * 32 + i];
        cnt[t] = c;
    }
    __syncthreads();
    if (t == 0) {
        int acc = 0;
        for (int c = 0; c < 64; c++) { base[c] = acc; acc += cnt[c]; }
        base[64] = acc;
        g_mcount = acc;
        g_mcount64 = (acc + 63) & ~63;
    }
    __syncthreads();
    if (t < 64) {
        int pos = base[t];
        for (int i = 0; i < 32; i++)
            if (sm[t * 32 + i]) g_midx[pos++] = t * 32 + i;
    }
    __syncthreads();
    int mc = base[64];
    for (int i = t; i < SEQ; i += 1024)
        if (i >= mc) g_midx[i] = 0;
}

// ---------------- fused gathered projections (Q,K,V), f32x2 ----------------
// 128x64 tile, K-step 16, 8x4 micro, acc packed over even/odd k.
__global__ __launch_bounds__(256, 2) void proj_kernel(
    const float* __restrict__ X,
    const float* __restrict__ Wq, const float* __restrict__ bq,
    const float* __restrict__ Wk, const float* __restrict__ bk,
    const float* __restrict__ Wv, const float* __restrict__ bv)
{
    __shared__ __align__(16) float Xs[128][18];
    __shared__ ull  WsP[16][65];      // WsP[kp][c] = (W[2kp][c], W[2kp+1][c])
    __shared__ int  ridx[128];

    const int t  = threadIdx.x;
    const int tx = t & 15, ty = t >> 4;
    const int m0 = blockIdx.y << 7;
    if (m0 >= g_mcount64) return;
    const int n0 = blockIdx.x << 6;

    const float *W, *bias; float* out;
    if (blockIdx.z == 0)      { W = Wq; bias = bq; out = g_Q; }
    else if (blockIdx.z == 1) { W = Wk; bias = bk; out = g_K; }
    else                      { W = Wv; bias = bv; out = g_V; }

    if (t < 128) ridx[t] = g_midx[m0 + t];
    __syncthreads();

    ull acc[8][4];
    #pragma unroll
    for (int i = 0; i < 8; i++)
        #pragma unroll
        for (int j = 0; j < 4; j++) acc[i][j] = 0ull;

    for (int k0 = 0; k0 < DM; k0 += 16) {
        // X tile (gathered rows)
        #pragma unroll
        for (int u = 0; u < 8; u++) {
            int r = (t >> 4) + u * 16;
            Xs[r][t & 15] = X[(size_t)ridx[r] * DM + k0 + (t & 15)];
        }
        // W tile as k-pairs
        #pragma unroll
        for (int u = 0; u < 2; u++) {
            int p = t + u * 256;
            int kp = p >> 6, c = p & 63;
            const float* wp = W + (size_t)(k0 + 2 * kp) * HD + n0 + c;
            WsP[kp][c] = packf2(wp[0], wp[HD]);
        }
        __syncthreads();
        #pragma unroll
        for (int kp = 0; kp < 8; kp++) {
            ull a[8], b[4];
            #pragma unroll
            for (int i = 0; i < 8; i++) a[i] = *(const ull*)&Xs[ty * 8 + i][2 * kp];
            #pragma unroll
            for (int j = 0; j < 4; j++) b[j] = WsP[kp][tx + 16 * j];
            #pragma unroll
            for (int i = 0; i < 8; i++)
                #pragma unroll
                for (int j = 0; j < 4; j++) fma2(acc[i][j], a[i], b[j]);
        }
        __syncthreads();
    }
    #pragma unroll
    for (int i = 0; i < 8; i++) {
        int row = m0 + ty * 8 + i;      // compacted row
        #pragma unroll
        for (int j = 0; j < 4; j++) {
            int col = n0 + tx + 16 * j;
            float v = f2sum(acc[i][j]) + bias[col];
            out[(size_t)((col >> 7) * SEQ + row) * DH + (col & 127)] = v;
        }
    }
}

// ---------------- mean(X) and mean-V via linearity ----------------
__global__ void xpart_kernel(const float* __restrict__ X)
{
    int j  = blockIdx.x * 256 + threadIdx.x;   // grid.x = 4
    int rb = blockIdx.y;                        // 8
    const float* p = X + (size_t)rb * 256 * DM + j;
    float s = 0.0f;
    #pragma unroll 8
    for (int r = 0; r < 256; r++) s += p[(size_t)r * DM];
    g_xpart[rb][j] = s;
}
__global__ void xmean_kernel(void)
{
    int j = blockIdx.x * 256 + threadIdx.x;    // grid 4
    float s = 0.0f;
    #pragma unroll
    for (int rb = 0; rb < 8; rb++) s += g_xpart[rb][j];
    g_xmean[j] = s * (1.0f / 2048.0f);
}
__global__ void vgemv_kernel(const float* __restrict__ Wv, const float* __restrict__ bv)
{
    __shared__ float xm[DM];
    int t = threadIdx.x;
    #pragma unroll
    for (int u = 0; u < 4; u++) xm[t + u * 256] = g_xmean[t + u * 256];
    __syncthreads();
    int c = blockIdx.x * 256 + t;              // grid 8
    float a0 = 0, a1 = 0, a2 = 0, a3 = 0;
    for (int j = 0; j < DM; j += 4) {
        a0 += xm[j + 0] * Wv[(size_t)(j + 0) * HD + c];
        a1 += xm[j + 1] * Wv[(size_t)(j + 1) * HD + c];
        a2 += xm[j + 2] * Wv[(size_t)(j + 2) * HD + c];
        a3 += xm[j + 3] * Wv[(size_t)(j + 3) * HD + c];
    }
    g_vmean[c] = (a0 + a1) + (a2 + a3) + bv[c];
}

// ---------------- score + argmin, f32x2 ----------------
// 128(q) x 64(k) tile per iteration; acc packed over even/odd d.
// dyn smem floats: Qs[128][130]@0, Ks[64][130]@16640, rv@24960(2048),
//                  ri@27008(2048), bestv@29056(128), besti@29184(128)
#define SC_FLOATS 29312

__global__ __launch_bounds__(256) void score_kernel(void)
{
    extern __shared__ __align__(16) float sm[];
    float* Qs    = sm;
    float* Ks    = sm + 16640;
    float* rv    = sm + 24960;
    int*   ri    = (int*)(sm + 27008);
    float* bestv = sm + 29056;
    int*   besti = (int*)(sm + 29184);

    const int t  = threadIdx.x;
    const int tx = t & 15, ty = t >> 4;
    const int h  = blockIdx.y;
    const int q0 = blockIdx.x << 7;
    const int mc   = g_mcount;
    const int mc64 = g_mcount64;
    if (q0 >= mc) return;

    // load Q tile [128][128] -> stride 130 (ull stores)
    const float* Qg = g_Q + (size_t)(h * SEQ + q0) * DH;
    #pragma unroll
    for (int u = 0; u < 16; u++) {
        int i = t + u * 256;
        float4 v = ((const float4*)Qg)[i];
        int r = i >> 5, dd = (i & 31) << 2;
        ull* p = (ull*)&Qs[r * 130 + dd];
        p[0] = packf2(v.x, v.y); p[1] = packf2(v.z, v.w);
    }
    if (t < 128) { bestv[t] = INFINITY; besti[t] = 0; }

    const int nkt = mc64 >> 6;
    for (int kt = 0; kt < nkt; kt++) {
        const int k0 = kt << 6;
        __syncthreads();
        const float* Kg = g_K + (size_t)(h * SEQ + k0) * DH;
        #pragma unroll
        for (int u = 0; u < 8; u++) {
            int i = t + u * 256;
            float4 v = ((const float4*)Kg)[i];
            int r = i >> 5, dd = (i & 31) << 2;
            ull* p = (ull*)&Ks[r * 130 + dd];
            p[0] = packf2(v.x, v.y); p[1] = packf2(v.z, v.w);
        }
        __syncthreads();

        ull acc[8][4];
        #pragma unroll
        for (int i = 0; i < 8; i++)
            #pragma unroll
            for (int j = 0; j < 4; j++) acc[i][j] = 0ull;

        #pragma unroll 4
        for (int dp = 0; dp < 64; dp++) {
            ull a[8], b[4];
            #pragma unroll
            for (int i = 0; i < 8; i++) a[i] = *(const ull*)&Qs[(ty * 8 + i) * 130 + 2 * dp];
            #pragma unroll
            for (int j = 0; j < 4; j++) b[j] = *(const ull*)&Ks[(tx + 16 * j) * 130 + 2 * dp];
            #pragma unroll
            for (int i = 0; i < 8; i++)
                #pragma unroll
                for (int j = 0; j < 4; j++) fma2(acc[i][j], a[i], b[j]);
        }

        // per-thread argmin over its 4 cols
        #pragma unroll
        for (int i = 0; i < 8; i++) {
            int row = ty * 8 + i;
            float bv_ = INFINITY; int bi = 0;
            #pragma unroll
            for (int j = 0; j < 4; j++) {
                int c = k0 + tx + 16 * j;
                float s = f2sum(acc[i][j]);
                s = (c < mc) ? s : INFINITY;
                if (s < bv_) { bv_ = s; bi = c; }
            }
            rv[row * 16 + tx] = bv_;
            ri[row * 16 + tx] = bi;
        }
        __syncthreads();
        if (t < 128) {
            float bv_ = bestv[t]; int bi = besti[t];
            #pragma unroll
            for (int p = 0; p < 16; p++) {
                float v = rv[t * 16 + p];
                if (v < bv_) { bv_ = v; bi = ri[t * 16 + p]; }
            }
            bestv[t] = bv_; besti[t] = bi;
        }
    }
    if (t < 128 && q0 + t < mc)
        g_kbest[h * SEQ + g_midx[q0 + t]] = besti[t];   // compacted k index
}

// ---------------- output assembly ----------------
__global__ void assemble_kernel(float* __restrict__ out)
{
    int s = blockIdx.x;
    int t = threadIdx.x;               // 256
    if (g_mask[s]) {
        #pragma unroll
        for (int i = 0; i < 8; i++) {
            int idx = i * 256 + t;     // h*128 + d
            int h = idx >> 7, d = idx & 127;
            int kb = g_kbest[h * SEQ + s];
            out[(size_t)s * HD + idx] = g_V[(size_t)(h * SEQ + kb) * DH + d];
        }
    } else {
        #pragma unroll
        for (int i = 0; i < 8; i++) {
            int idx = i * 256 + t;
            out[(size_t)s * HD + idx] = g_vmean[idx];
        }
    }
}

// ---------------- launch ----------------
extern "C" void kernel_launch(void* const* d_in, const int* in_sizes, int n_in,
                              void* d_out, int out_size)
{
    const float* X          = (const float*)d_in[0];
    const unsigned char* mp = (const unsigned char*)d_in[1];
    const float* Wq = (const float*)d_in[2];
    const float* bq = (const float*)d_in[3];
    const float* Wk = (const float*)d_in[4];
    const float* bk = (const float*)d_in[5];
    const float* Wv = (const float*)d_in[6];
    const float* bv = (const float*)d_in[7];
    float* out = (float*)d_out;

    mask_setup_kernel<<<1, 1024>>>(mp);

    xpart_kernel<<<dim3(4, 8), 256>>>(X);
    xmean_kernel<<<4, 256>>>();

    proj_kernel<<<dim3(HD / 64, SEQ / 128, 3), 256>>>(X, Wq, bq, Wk, bk, Wv, bv);

    vgemv_kernel<<<8, 256>>>(Wv, bv);

    const int sc_bytes = SC_FLOATS * (int)sizeof(float);
    cudaFuncSetAttribute(score_kernel, cudaFuncAttributeMaxDynamicSharedMemorySize, sc_bytes);
    score_kernel<<<dim3(SEQ / 128, NH), 256, sc_bytes>>>();

    assemble_kernel<<<SEQ, 256>>>(out);
}

// round 6
// speedup vs baseline: 3.5965x; 1.2061x over previous
#include <cuda_runtime.h>
#include <math.h>

typedef unsigned long long ull;

#define SEQ   2048
#define DM    1024
#define NH    16
#define DH    128
#define HD    2048   // NH*DH

// ---------------- scratch ----------------
__device__ float g_Q[NH * SEQ * DH];   // compacted masked rows, head-major
__device__ float g_K[NH * SEQ * DH];
__device__ float g_V[NH * SEQ * DH];
__device__ float g_xpart[8][DM];
__device__ float g_xmean[DM];
__device__ float g_vpart[4][HD];
__device__ float g_vmean[HD];
__device__ int   g_mask[SEQ];
__device__ int   g_midx[SEQ];
__device__ int   g_kbest[NH * SEQ];
__device__ int   g_mcount;
__device__ int   g_mcount64;

// ---------------- f32x2 helpers ----------------
__device__ __forceinline__ void fma2(ull& d, ull a, ull b) {
    asm("fma.rn.f32x2 %0, %1, %2, %0;" : "+l"(d) : "l"(a), "l"(b));
}
__device__ __forceinline__ ull packf2(float lo, float hi) {
    ull r; asm("mov.b64 %0, {%1, %2};" : "=l"(r) : "f"(lo), "f"(hi)); return r;
}
__device__ __forceinline__ ull add2(ull a, ull b) {
    ull r; asm("add.rn.f32x2 %0, %1, %2;" : "=l"(r) : "l"(a), "l"(b)); return r;
}
__device__ __forceinline__ float f2sum(ull v) {
    float lo, hi; asm("mov.b64 {%0, %1}, %2;" : "=f"(lo), "=f"(hi) : "l"(v));
    return lo + hi;
}

// ---------------- mask decode + compaction ----------------
__global__ void mask_setup_kernel(const unsigned char* __restrict__ p)
{
    __shared__ int sm[SEQ];
    __shared__ int cnt[64];
    __shared__ int base[65];
    __shared__ int not_i32, not_f32;
    int t = threadIdx.x;               // 1024 threads
    if (t == 0) { not_i32 = 0; not_f32 = 0; }
    __syncthreads();
    if (t < 512) {
        unsigned w = ((const unsigned*)p)[t];
        if (!(w == 0u || w == 1u))          atomicExch(&not_i32, 1);
        if (!(w == 0u || w == 0x3F800000u)) atomicExch(&not_f32, 1);
    }
    __syncthreads();
    int cls = (!not_i32) ? 0 : ((!not_f32) ? 1 : 2);
    for (int i = t; i < SEQ; i += 1024) {
        int v;
        if (cls == 0)      v = (((const int*)p)[i]   != 0);
        else if (cls == 1) v = (((const float*)p)[i] != 0.0f);
        else               v = (p[i] != 0);
        sm[i] = v; g_mask[i] = v;
    }
    __syncthreads();
    if (t < 64) {
        int c = 0;
        for (int i = 0; i < 32; i++) c += sm[t * 32 + i];
        cnt[t] = c;
    }
    __syncthreads();
    if (t == 0) {
        int acc = 0;
        for (int c = 0; c < 64; c++) { base[c] = acc; acc += cnt[c]; }
        base[64] = acc;
        g_mcount = acc;
        g_mcount64 = (acc + 63) & ~63;
    }
    __syncthreads();
    if (t < 64) {
        int pos = base[t];
        for (int i = 0; i < 32; i++)
            if (sm[t * 32 + i]) g_midx[pos++] = t * 32 + i;
    }
    __syncthreads();
    int mc = base[64];
    for (int i = t; i < SEQ; i += 1024)
        if (i >= mc) g_midx[i] = 0;
}

// ---------------- fused gathered projections (Q,K,V), n-packed f32x2 ----------------
// Tile 64(m) x 256(n), k-step 32. Thread: 4 rows x 8 ull-cols.
// smem (dynamic): Xd[64][33] ull @0 (2112 ull), Wp[32][129] ull @2112 (4128 ull),
//                 ridx @ 6240*2 ints.  total = (2112+4128)*8 + 256 = 50176 B
#define PROJ_SMEM_BYTES (6240 * 8 + 256)

__global__ __launch_bounds__(256, 2) void proj_kernel(
    const float* __restrict__ X,
    const float* __restrict__ Wq, const float* __restrict__ bq,
    const float* __restrict__ Wk, const float* __restrict__ bk,
    const float* __restrict__ Wv, const float* __restrict__ bv)
{
    extern __shared__ __align__(16) ull dsm[];
    ull* Xd   = dsm;            // [64][33]
    ull* Wp   = dsm + 2112;     // [32][129]
    int* ridx = (int*)(dsm + 6240);

    const int t  = threadIdx.x;
    const int tx = t & 15, ty = t >> 4;
    const int m0 = blockIdx.y << 6;
    if (m0 >= g_mcount64) return;
    const int n0 = blockIdx.x << 8;

    const float *W, *bias; float* out;
    if (blockIdx.z == 0)      { W = Wq; bias = bq; out = g_Q; }
    else if (blockIdx.z == 1) { W = Wk; bias = bk; out = g_K; }
    else                      { W = Wv; bias = bv; out = g_V; }

    if (t < 64) ridx[t] = g_midx[m0 + t];
    __syncthreads();

    ull acc[4][8];
    #pragma unroll
    for (int i = 0; i < 4; i++)
        #pragma unroll
        for (int j = 0; j < 8; j++) acc[i][j] = 0ull;

    const int r0 = ty << 2;

    for (int k0 = 0; k0 < DM; k0 += 32) {
        // X tile: 64 rows x 32 k, duplicated pairs
        #pragma unroll
        for (int u = 0; u < 8; u++) {
            int i = t + u * 256;           // 0..2047
            int r = i >> 5, kk = i & 31;
            float x = X[(size_t)ridx[r] * DM + k0 + kk];
            Xd[r * 33 + kk] = packf2(x, x);
        }
        // W tile: 32 k-rows x 128 col-pairs (natural float2)
        #pragma unroll
        for (int u = 0; u < 16; u++) {
            int i = t + u * 256;           // 0..4095
            int kk = i >> 7, cp = i & 127;
            Wp[kk * 129 + cp] = *(const ull*)(W + (size_t)(k0 + kk) * HD + n0 + 2 * cp);
        }
        __syncthreads();
        #pragma unroll 4
        for (int kk = 0; kk < 32; kk++) {
            ull a0 = Xd[(r0 + 0) * 33 + kk];
            ull a1 = Xd[(r0 + 1) * 33 + kk];
            ull a2 = Xd[(r0 + 2) * 33 + kk];
            ull a3 = Xd[(r0 + 3) * 33 + kk];
            const ull* wr = Wp + kk * 129 + tx;
            #pragma unroll
            for (int j = 0; j < 8; j++) {
                ull b = wr[16 * j];
                fma2(acc[0][j], a0, b);
                fma2(acc[1][j], a1, b);
                fma2(acc[2][j], a2, b);
                fma2(acc[3][j], a3, b);
            }
        }
        __syncthreads();
    }
    // epilogue: col-pair cp = tx + 16j, float cols (n0+2cp, n0+2cp+1) same head
    #pragma unroll
    for (int j = 0; j < 8; j++) {
        int cp  = tx + 16 * j;
        int col = n0 + 2 * cp;
        ull bpair = *(const ull*)(bias + col);
        int h = col >> 7, d = col & 127;
        ull* dst = (ull*)(out + (size_t)(h * SEQ + m0 + r0) * DH + d);
        #pragma unroll
        for (int i = 0; i < 4; i++)
            dst[i * (DH / 2) * 1] = add2(acc[i][j], bpair),
            dst = dst;   // keep simple
        // note: rows differ by full DH stride in floats = DH/2 ull
        // (written explicitly below to avoid aliasing confusion)
    }
    // The loop above already stored row r0 only; store remaining rows correctly:
    // (re-store all four rows explicitly — cheap, overwrites row r0 identically)
    #pragma unroll
    for (int j = 0; j < 8; j++) {
        int cp  = tx + 16 * j;
        int col = n0 + 2 * cp;
        ull bpair = *(const ull*)(bias + col);
        int h = col >> 7, d = col & 127;
        #pragma unroll
        for (int i = 0; i < 4; i++) {
            ull* dst = (ull*)(out + (size_t)(h * SEQ + m0 + r0 + i) * DH + d);
            *dst = add2(acc[i][j], bpair);
        }
    }
}

// ---------------- mean(X) and mean-V via linearity ----------------
__global__ void xpart_kernel(const float* __restrict__ X)
{
    int j  = blockIdx.x * 256 + threadIdx.x;   // grid.x = 4
    int rb = blockIdx.y;                        // 8
    const float* p = X + (size_t)rb * 256 * DM + j;
    float s = 0.0f;
    #pragma unroll 8
    for (int r = 0; r < 256; r++) s += p[(size_t)r * DM];
    g_xpart[rb][j] = s;
}
__global__ void xmean_kernel(void)
{
    int j = blockIdx.x * 256 + threadIdx.x;    // grid 4
    float s = 0.0f;
    #pragma unroll
    for (int rb = 0; rb < 8; rb++) s += g_xpart[rb][j];
    g_xmean[j] = s * (1.0f / 2048.0f);
}
__global__ void vgemv_kernel(const float* __restrict__ Wv)
{
    __shared__ float xm[256];
    int t = threadIdx.x;
    int part = blockIdx.y;                     // 4 k-slices of 256
    xm[t] = g_xmean[part * 256 + t];
    __syncthreads();
    int c = blockIdx.x * 256 + t;              // grid.x 8
    float a0 = 0, a1 = 0, a2 = 0, a3 = 0;
    const float* Wp = Wv + (size_t)part * 256 * HD + c;
    for (int j = 0; j < 256; j += 4) {
        a0 += xm[j + 0] * Wp[(size_t)(j + 0) * HD];
        a1 += xm[j + 1] * Wp[(size_t)(j + 1) * HD];
        a2 += xm[j + 2] * Wp[(size_t)(j + 2) * HD];
        a3 += xm[j + 3] * Wp[(size_t)(j + 3) * HD];
    }
    g_vpart[part][c] = (a0 + a1) + (a2 + a3);
}
__global__ void vcombine_kernel(const float* __restrict__ bv)
{
    int c = blockIdx.x * 256 + threadIdx.x;    // grid 8
    g_vmean[c] = ((g_vpart[0][c] + g_vpart[1][c]) + (g_vpart[2][c] + g_vpart[3][c])) + bv[c];
}

// ---------------- score + argmin, f32x2 (k-packed; unchanged from R3) ----------------
#define SC_FLOATS 29312

__global__ __launch_bounds__(256) void score_kernel(void)
{
    extern __shared__ __align__(16) float sm[];
    float* Qs    = sm;
    float* Ks    = sm + 16640;
    float* rv    = sm + 24960;
    int*   ri    = (int*)(sm + 27008);
    float* bestv = sm + 29056;
    int*   besti = (int*)(sm + 29184);

    const int t  = threadIdx.x;
    const int tx = t & 15, ty = t >> 4;
    const int h  = blockIdx.y;
    const int q0 = blockIdx.x << 7;
    const int mc   = g_mcount;
    const int mc64 = g_mcount64;
    if (q0 >= mc) return;

    const float* Qg = g_Q + (size_t)(h * SEQ + q0) * DH;
    #pragma unroll
    for (int u = 0; u < 16; u++) {
        int i = t + u * 256;
        float4 v = ((const float4*)Qg)[i];
        int r = i >> 5, dd = (i & 31) << 2;
        ull* p = (ull*)&Qs[r * 130 + dd];
        p[0] = packf2(v.x, v.y); p[1] = packf2(v.z, v.w);
    }
    if (t < 128) { bestv[t] = INFINITY; besti[t] = 0; }

    const int nkt = mc64 >> 6;
    for (int kt = 0; kt < nkt; kt++) {
        const int k0 = kt << 6;
        __syncthreads();
        const float* Kg = g_K + (size_t)(h * SEQ + k0) * DH;
        #pragma unroll
        for (int u = 0; u < 8; u++) {
            int i = t + u * 256;
            float4 v = ((const float4*)Kg)[i];
            int r = i >> 5, dd = (i & 31) << 2;
            ull* p = (ull*)&Ks[r * 130 + dd];
            p[0] = packf2(v.x, v.y); p[1] = packf2(v.z, v.w);
        }
        __syncthreads();

        ull acc[8][4];
        #pragma unroll
        for (int i = 0; i < 8; i++)
            #pragma unroll
            for (int j = 0; j < 4; j++) acc[i][j] = 0ull;

        #pragma unroll 4
        for (int dp = 0; dp < 64; dp++) {
            ull a[8], b[4];
            #pragma unroll
            for (int i = 0; i < 8; i++) a[i] = *(const ull*)&Qs[(ty * 8 + i) * 130 + 2 * dp];
            #pragma unroll
            for (int j = 0; j < 4; j++) b[j] = *(const ull*)&Ks[(tx + 16 * j) * 130 + 2 * dp];
            #pragma unroll
            for (int i = 0; i < 8; i++)
                #pragma unroll
                for (int j = 0; j < 4; j++) fma2(acc[i][j], a[i], b[j]);
        }

        #pragma unroll
        for (int i = 0; i < 8; i++) {
            int row = ty * 8 + i;
            float bv_ = INFINITY; int bi = 0;
            #pragma unroll
            for (int j = 0; j < 4; j++) {
                int c = k0 + tx + 16 * j;
                float s = f2sum(acc[i][j]);
                s = (c < mc) ? s : INFINITY;
                if (s < bv_) { bv_ = s; bi = c; }
            }
            rv[row * 16 + tx] = bv_;
            ri[row * 16 + tx] = bi;
        }
        __syncthreads();
        if (t < 128) {
            float bv_ = bestv[t]; int bi = besti[t];
            #pragma unroll
            for (int p = 0; p < 16; p++) {
                float v = rv[t * 16 + p];
                if (v < bv_) { bv_ = v; bi = ri[t * 16 + p]; }
            }
            bestv[t] = bv_; besti[t] = bi;
        }
    }
    if (t < 128 && q0 + t < mc)
        g_kbest[h * SEQ + g_midx[q0 + t]] = besti[t];
}

// ---------------- output assembly ----------------
__global__ void assemble_kernel(float* __restrict__ out)
{
    int s = blockIdx.x;
    int t = threadIdx.x;               // 256
    if (g_mask[s]) {
        #pragma unroll
        for (int i = 0; i < 8; i++) {
            int idx = i * 256 + t;
            int h = idx >> 7, d = idx & 127;
            int kb = g_kbest[h * SEQ + s];
            out[(size_t)s * HD + idx] = g_V[(size_t)(h * SEQ + kb) * DH + d];
        }
    } else {
        #pragma unroll
        for (int i = 0; i < 8; i++) {
            int idx = i * 256 + t;
            out[(size_t)s * HD + idx] = g_vmean[idx];
        }
    }
}

// ---------------- launch ----------------
extern "C" void kernel_launch(void* const* d_in, const int* in_sizes, int n_in,
                              void* d_out, int out_size)
{
    const float* X          = (const float*)d_in[0];
    const unsigned char* mp = (const unsigned char*)d_in[1];
    const float* Wq = (const float*)d_in[2];
    const float* bq = (const float*)d_in[3];
    const float* Wk = (const float*)d_in[4];
    const float* bk = (const float*)d_in[5];
    const float* Wv = (const float*)d_in[6];
    const float* bv = (const float*)d_in[7];
    float* out = (float*)d_out;

    mask_setup_kernel<<<1, 1024>>>(mp);

    xpart_kernel<<<dim3(4, 8), 256>>>(X);
    xmean_kernel<<<4, 256>>>();

    cudaFuncSetAttribute(proj_kernel, cudaFuncAttributeMaxDynamicSharedMemorySize, PROJ_SMEM_BYTES);
    proj_kernel<<<dim3(HD / 256, SEQ / 64, 3), 256, PROJ_SMEM_BYTES>>>(X, Wq, bq, Wk, bk, Wv, bv);

    vgemv_kernel<<<dim3(8, 4), 256>>>(Wv);
    vcombine_kernel<<<8, 256>>>(bv);

    const int sc_bytes = SC_FLOATS * (int)sizeof(float);
    cudaFuncSetAttribute(score_kernel, cudaFuncAttributeMaxDynamicSharedMemorySize, sc_bytes);
    score_kernel<<<dim3(SEQ / 128, NH), 256, sc_bytes>>>();

    assemble_kernel<<<SEQ, 256>>>(out);
}

// round 7
// speedup vs baseline: 3.7925x; 1.0545x over previous
#include <cuda_runtime.h>
#include <math.h>

typedef unsigned long long ull;

#define SEQ   2048
#define DM    1024
#define NH    16
#define DH    128
#define HD    2048   // NH*DH

// ---------------- scratch ----------------
__device__ float g_Q[NH * SEQ * DH];   // compacted masked rows, head-major
__device__ float g_K[NH * SEQ * DH];
__device__ float g_V[NH * SEQ * DH];
__device__ float g_xpart[8][DM];
__device__ float g_xmean[DM];
__device__ float g_vpart[4][HD];
__device__ float g_vmean[HD];
__device__ int   g_mask[SEQ];
__device__ int   g_midx[SEQ];
__device__ int   g_kbest[NH * SEQ];
__device__ int   g_mcount;
__device__ int   g_mcount64;

// ---------------- f32x2 helpers ----------------
__device__ __forceinline__ void fma2(ull& d, ull a, ull b) {
    asm("fma.rn.f32x2 %0, %1, %2, %0;" : "+l"(d) : "l"(a), "l"(b));
}
__device__ __forceinline__ ull packf2(float lo, float hi) {
    ull r; asm("mov.b64 %0, {%1, %2};" : "=l"(r) : "f"(lo), "f"(hi)); return r;
}
__device__ __forceinline__ ull add2(ull a, ull b) {
    ull r; asm("add.rn.f32x2 %0, %1, %2;" : "=l"(r) : "l"(a), "l"(b)); return r;
}
__device__ __forceinline__ float f2sum(ull v) {
    float lo, hi; asm("mov.b64 {%0, %1}, %2;" : "=f"(lo), "=f"(hi) : "l"(v));
    return lo + hi;
}

// ---------------- mask decode + compaction ----------------
__global__ void mask_setup_kernel(const unsigned char* __restrict__ p)
{
    __shared__ int sm[SEQ];
    __shared__ int cnt[64];
    __shared__ int base[65];
    __shared__ int not_i32, not_f32;
    int t = threadIdx.x;               // 1024 threads
    if (t == 0) { not_i32 = 0; not_f32 = 0; }
    __syncthreads();
    if (t < 512) {
        unsigned w = ((const unsigned*)p)[t];
        if (!(w == 0u || w == 1u))          atomicExch(&not_i32, 1);
        if (!(w == 0u || w == 0x3F800000u)) atomicExch(&not_f32, 1);
    }
    __syncthreads();
    int cls = (!not_i32) ? 0 : ((!not_f32) ? 1 : 2);
    for (int i = t; i < SEQ; i += 1024) {
        int v;
        if (cls == 0)      v = (((const int*)p)[i]   != 0);
        else if (cls == 1) v = (((const float*)p)[i] != 0.0f);
        else               v = (p[i] != 0);
        sm[i] = v; g_mask[i] = v;
    }
    __syncthreads();
    if (t < 64) {
        int c = 0;
        for (int i = 0; i < 32; i++) c += sm[t * 32 + i];
        cnt[t] = c;
    }
    __syncthreads();
    if (t == 0) {
        int acc = 0;
        for (int c = 0; c < 64; c++) { base[c] = acc; acc += cnt[c]; }
        base[64] = acc;
        g_mcount = acc;
        g_mcount64 = (acc + 63) & ~63;
    }
    __syncthreads();
    if (t < 64) {
        int pos = base[t];
        for (int i = 0; i < 32; i++)
            if (sm[t * 32 + i]) g_midx[pos++] = t * 32 + i;
    }
    __syncthreads();
    int mc = base[64];
    for (int i = t; i < SEQ; i += 1024)
        if (i >= mc) g_midx[i] = 0;
}

// ---------------- fused gathered projections (Q,K,V), n-packed f32x2 ----------------
// Tile 64(m) x 128(n floats = 64 pairs), k-step 32. Thread: 4 rows x 4 ull-cols.
// smem: Xd[64][33] ull @0 (2112), Wp[32][65] ull @2112 (2080), ridx @4192 (64 int)
// bytes = 4192*8 + 256 = 33792
#define PROJ_SMEM_BYTES (4192 * 8 + 256)

__global__ __launch_bounds__(256, 3) void proj_kernel(
    const float* __restrict__ X,
    const float* __restrict__ Wq, const float* __restrict__ bq,
    const float* __restrict__ Wk, const float* __restrict__ bk,
    const float* __restrict__ Wv, const float* __restrict__ bv)
{
    extern __shared__ __align__(16) ull dsm[];
    ull* Xd   = dsm;            // [64][33]
    ull* Wp   = dsm + 2112;     // [32][65]
    int* ridx = (int*)(dsm + 4192);

    const int t  = threadIdx.x;
    const int tx = t & 15, ty = t >> 4;
    const int m0 = blockIdx.y << 6;
    if (m0 >= g_mcount64) return;
    const int n0 = blockIdx.x << 7;      // 128 floats per n-tile

    const float *W, *bias; float* out;
    if (blockIdx.z == 0)      { W = Wq; bias = bq; out = g_Q; }
    else if (blockIdx.z == 1) { W = Wk; bias = bk; out = g_K; }
    else                      { W = Wv; bias = bv; out = g_V; }

    if (t < 64) ridx[t] = g_midx[m0 + t];
    __syncthreads();

    ull acc[4][4];
    #pragma unroll
    for (int i = 0; i < 4; i++)
        #pragma unroll
        for (int j = 0; j < 4; j++) acc[i][j] = 0ull;

    const int r0 = ty << 2;

    for (int k0 = 0; k0 < DM; k0 += 32) {
        // X tile: 64 rows x 32 k, duplicated pairs
        #pragma unroll
        for (int u = 0; u < 8; u++) {
            int i = t + u * 256;           // 0..2047
            int r = i >> 5, kk = i & 31;
            float x = X[(size_t)ridx[r] * DM + k0 + kk];
            Xd[r * 33 + kk] = packf2(x, x);
        }
        // W tile: 32 k-rows x 64 col-pairs (natural float2)
        #pragma unroll
        for (int u = 0; u < 8; u++) {
            int i = t + u * 256;           // 0..2047
            int kk = i >> 6, cp = i & 63;
            Wp[kk * 65 + cp] = *(const ull*)(W + (size_t)(k0 + kk) * HD + n0 + 2 * cp);
        }
        __syncthreads();
        #pragma unroll 4
        for (int kk = 0; kk < 32; kk++) {
            ull a0 = Xd[(r0 + 0) * 33 + kk];
            ull a1 = Xd[(r0 + 1) * 33 + kk];
            ull a2 = Xd[(r0 + 2) * 33 + kk];
            ull a3 = Xd[(r0 + 3) * 33 + kk];
            const ull* wr = Wp + kk * 65 + tx;
            #pragma unroll
            for (int j = 0; j < 4; j++) {
                ull b = wr[16 * j];
                fma2(acc[0][j], a0, b);
                fma2(acc[1][j], a1, b);
                fma2(acc[2][j], a2, b);
                fma2(acc[3][j], a3, b);
            }
        }
        __syncthreads();
    }
    // epilogue: col-pair cp = tx + 16j -> float cols (n0+2cp, n0+2cp+1), same head
    #pragma unroll
    for (int j = 0; j < 4; j++) {
        int cp  = tx + 16 * j;
        int col = n0 + 2 * cp;
        ull bpair = *(const ull*)(bias + col);
        int h = col >> 7, d = col & 127;
        #pragma unroll
        for (int i = 0; i < 4; i++) {
            ull* dst = (ull*)(out + (size_t)(h * SEQ + m0 + r0 + i) * DH + d);
            *dst = add2(acc[i][j], bpair);
        }
    }
}

// ---------------- mean(X) and mean-V via linearity ----------------
__global__ void xpart_kernel(const float* __restrict__ X)
{
    int j  = blockIdx.x * 256 + threadIdx.x;   // grid.x = 4
    int rb = blockIdx.y;                        // 8
    const float* p = X + (size_t)rb * 256 * DM + j;
    float s = 0.0f;
    #pragma unroll 8
    for (int r = 0; r < 256; r++) s += p[(size_t)r * DM];
    g_xpart[rb][j] = s;
}
__global__ void xmean_kernel(void)
{
    int j = blockIdx.x * 256 + threadIdx.x;    // grid 4
    float s = 0.0f;
    #pragma unroll
    for (int rb = 0; rb < 8; rb++) s += g_xpart[rb][j];
    g_xmean[j] = s * (1.0f / 2048.0f);
}
__global__ void vgemv_kernel(const float* __restrict__ Wv)
{
    __shared__ float xm[256];
    int t = threadIdx.x;
    int part = blockIdx.y;                     // 4 k-slices of 256
    xm[t] = g_xmean[part * 256 + t];
    __syncthreads();
    int c = blockIdx.x * 256 + t;              // grid.x 8
    float a0 = 0, a1 = 0, a2 = 0, a3 = 0;
    const float* Wp = Wv + (size_t)part * 256 * HD + c;
    for (int j = 0; j < 256; j += 4) {
        a0 += xm[j + 0] * Wp[(size_t)(j + 0) * HD];
        a1 += xm[j + 1] * Wp[(size_t)(j + 1) * HD];
        a2 += xm[j + 2] * Wp[(size_t)(j + 2) * HD];
        a3 += xm[j + 3] * Wp[(size_t)(j + 3) * HD];
    }
    g_vpart[part][c] = (a0 + a1) + (a2 + a3);
}
__global__ void vcombine_kernel(const float* __restrict__ bv)
{
    int c = blockIdx.x * 256 + threadIdx.x;    // grid 8
    g_vmean[c] = ((g_vpart[0][c] + g_vpart[1][c]) + (g_vpart[2][c] + g_vpart[3][c])) + bv[c];
}

// ---------------- score + argmin, f32x2, 64q x 64k tiles, 2 CTAs/SM ----------------
// smem floats: Qs[64][130]@0 (8320), Ks[64][130]@8320 (8320), rv@16640 (1024),
//              ri@17664 (1024), bestv@18688 (64), besti@18752 (64)  -> 18816 floats
#define SC_FLOATS 18816

__global__ __launch_bounds__(256, 2) void score_kernel(void)
{
    extern __shared__ __align__(16) float sm[];
    float* Qs    = sm;
    float* Ks    = sm + 8320;
    float* rv    = sm + 16640;
    int*   ri    = (int*)(sm + 17664);
    float* bestv = sm + 18688;
    int*   besti = (int*)(sm + 18752);

    const int t  = threadIdx.x;
    const int tx = t & 15, ty = t >> 4;
    const int h  = blockIdx.y;
    const int q0 = blockIdx.x << 6;
    const int mc   = g_mcount;
    const int mc64 = g_mcount64;
    if (q0 >= mc) return;

    // load Q tile [64][128] -> stride 130 floats (ull stores)
    const float* Qg = g_Q + (size_t)(h * SEQ + q0) * DH;
    #pragma unroll
    for (int u = 0; u < 8; u++) {
        int i = t + u * 256;               // float4 idx 0..2047
        float4 v = ((const float4*)Qg)[i];
        int r = i >> 5, dd = (i & 31) << 2;
        ull* p = (ull*)&Qs[r * 130 + dd];
        p[0] = packf2(v.x, v.y); p[1] = packf2(v.z, v.w);
    }
    if (t < 64) { bestv[t] = INFINITY; besti[t] = 0; }

    const int r0 = ty << 2;
    const int nkt = mc64 >> 6;
    for (int kt = 0; kt < nkt; kt++) {
        const int k0 = kt << 6;
        __syncthreads();
        const float* Kg = g_K + (size_t)(h * SEQ + k0) * DH;
        #pragma unroll
        for (int u = 0; u < 8; u++) {
            int i = t + u * 256;
            float4 v = ((const float4*)Kg)[i];
            int r = i >> 5, dd = (i & 31) << 2;
            ull* p = (ull*)&Ks[r * 130 + dd];
            p[0] = packf2(v.x, v.y); p[1] = packf2(v.z, v.w);
        }
        __syncthreads();

        ull acc[4][4];
        #pragma unroll
        for (int i = 0; i < 4; i++)
            #pragma unroll
            for (int j = 0; j < 4; j++) acc[i][j] = 0ull;

        #pragma unroll 4
        for (int dp = 0; dp < 64; dp++) {
            ull a0 = *(const ull*)&Qs[(r0 + 0) * 130 + 2 * dp];
            ull a1 = *(const ull*)&Qs[(r0 + 1) * 130 + 2 * dp];
            ull a2 = *(const ull*)&Qs[(r0 + 2) * 130 + 2 * dp];
            ull a3 = *(const ull*)&Qs[(r0 + 3) * 130 + 2 * dp];
            #pragma unroll
            for (int j = 0; j < 4; j++) {
                ull b = *(const ull*)&Ks[(tx + 16 * j) * 130 + 2 * dp];
                fma2(acc[0][j], a0, b);
                fma2(acc[1][j], a1, b);
                fma2(acc[2][j], a2, b);
                fma2(acc[3][j], a3, b);
            }
        }

        // per-thread argmin over its 4 cols, per row
        #pragma unroll
        for (int i = 0; i < 4; i++) {
            int row = r0 + i;
            float bv_ = INFINITY; int bi = 0;
            #pragma unroll
            for (int j = 0; j < 4; j++) {
                int c = k0 + tx + 16 * j;
                float s = f2sum(acc[i][j]);
                s = (c < mc) ? s : INFINITY;
                if (s < bv_) { bv_ = s; bi = c; }
            }
            rv[row * 16 + tx] = bv_;
            ri[row * 16 + tx] = bi;
        }
        __syncthreads();
        if (t < 64) {
            float bv_ = bestv[t]; int bi = besti[t];
            #pragma unroll
            for (int p = 0; p < 16; p++) {
                float v = rv[t * 16 + p];
                if (v < bv_) { bv_ = v; bi = ri[t * 16 + p]; }
            }
            bestv[t] = bv_; besti[t] = bi;
        }
    }
    if (t < 64 && q0 + t < mc)
        g_kbest[h * SEQ + g_midx[q0 + t]] = besti[t];
}

// ---------------- output assembly ----------------
__global__ void assemble_kernel(float* __restrict__ out)
{
    int s = blockIdx.x;
    int t = threadIdx.x;               // 256
    if (g_mask[s]) {
        #pragma unroll
        for (int i = 0; i < 8; i++) {
            int idx = i * 256 + t;
            int h = idx >> 7, d = idx & 127;
            int kb = g_kbest[h * SEQ + s];
            out[(size_t)s * HD + idx] = g_V[(size_t)(h * SEQ + kb) * DH + d];
        }
    } else {
        #pragma unroll
        for (int i = 0; i < 8; i++) {
            int idx = i * 256 + t;
            out[(size_t)s * HD + idx] = g_vmean[idx];
        }
    }
}

// ---------------- launch ----------------
extern "C" void kernel_launch(void* const* d_in, const int* in_sizes, int n_in,
                              void* d_out, int out_size)
{
    const float* X          = (const float*)d_in[0];
    const unsigned char* mp = (const unsigned char*)d_in[1];
    const float* Wq = (const float*)d_in[2];
    const float* bq = (const float*)d_in[3];
    const float* Wk = (const float*)d_in[4];
    const float* bk = (const float*)d_in[5];
    const float* Wv = (const float*)d_in[6];
    const float* bv = (const float*)d_in[7];
    float* out = (float*)d_out;

    mask_setup_kernel<<<1, 1024>>>(mp);

    xpart_kernel<<<dim3(4, 8), 256>>>(X);
    xmean_kernel<<<4, 256>>>();

    cudaFuncSetAttribute(proj_kernel, cudaFuncAttributeMaxDynamicSharedMemorySize, PROJ_SMEM_BYTES);
    proj_kernel<<<dim3(HD / 128, SEQ / 64, 3), 256, PROJ_SMEM_BYTES>>>(X, Wq, bq, Wk, bk, Wv, bv);

    vgemv_kernel<<<dim3(8, 4), 256>>>(Wv);
    vcombine_kernel<<<8, 256>>>(bv);

    const int sc_bytes = SC_FLOATS * (int)sizeof(float);
    cudaFuncSetAttribute(score_kernel, cudaFuncAttributeMaxDynamicSharedMemorySize, sc_bytes);
    score_kernel<<<dim3(SEQ / 64, NH), 256, sc_bytes>>>();

    assemble_kernel<<<SEQ, 256>>>(out);
}